// round 3
// baseline (speedup 1.0000x reference)
#include <cuda_runtime.h>

#define BATCH  64
#define NRES   4096
#define TSTEPS 128
#define NCLS   10
#define BETA   0.9f
#define THRESH 1.0f
#define BK 32
#define BN 32

// Persistent device scratch (no allocation — __device__ globals).
__device__ float g_S[2][BATCH * NRES];   // spike matrices, double buffered
__device__ float g_vr[BATCH * NRES];     // reservoir membrane potentials
__device__ float g_vc[BATCH * NCLS];     // classifier membrane potentials

// ---------------------------------------------------------------------------
// Init: zero S[0], v_r, v_c, out. Graph replays re-run this node, so every
// replay starts from identical state.
// ---------------------------------------------------------------------------
__global__ __launch_bounds__(256) void init_kernel(float* __restrict__ out) {
    int i = blockIdx.x * 256 + threadIdx.x;
    if (i < BATCH * NRES) {
        g_S[0][i] = 0.0f;
        g_vr[i]   = 0.0f;
    }
    if (i < BATCH * NCLS) {
        g_vc[i] = 0.0f;
        out[i]  = 0.0f;
    }
}

// ---------------------------------------------------------------------------
// Reservoir step t:
//   cur[b,n] = sum_k S_cur[b,k]*W_res[n,k] + x[b,t]*W_in[n]
//   v = BETA*v + cur ; s = (v>=1) ; v *= (1-s) ; S_next[b,n] = s
// 128 CTAs (BN=32 columns each), 256 threads, microtile 4 batches x 2 cols.
// Deterministic: fixed ascending-k fp32 FMA order, no atomics.
// ---------------------------------------------------------------------------
__global__ __launch_bounds__(256) void step_reservoir(
    const float* __restrict__ x,
    const float* __restrict__ W_in,
    const float* __restrict__ W_res,
    int t)
{
    // S_sm row stride = 68 floats = 272 B (16B multiple -> float4-aligned reads).
    __shared__ __align__(16) float S_sm[BK][BATCH + 4];
    // W_sm row stride = 37 floats: gcd(37,32)=1 -> conflict-free k-major stores.
    __shared__ float W_sm[BK][BN + 5];

    const float* __restrict__ Scur = g_S[t & 1];
    float* __restrict__       Snxt = g_S[(t + 1) & 1];

    const int n0  = blockIdx.x * BN;
    const int tid = threadIdx.x;
    const int tx  = tid & 15;   // batch group: b = 4*tx + i
    const int ty  = tid >> 4;   // column group: n = n0 + 2*ty + j

    float acc[4][2];
#pragma unroll
    for (int i = 0; i < 4; i++)
#pragma unroll
        for (int j = 0; j < 2; j++) acc[i][j] = 0.0f;

    for (int k0 = 0; k0 < NRES; k0 += BK) {
        // S tile: BK x BATCH = 2048 floats, 8 per thread, coalesced on k
#pragma unroll
        for (int r = 0; r < 8; r++) {
            int i  = tid + 256 * r;
            int bb = i >> 5;
            int kk = i & 31;
            S_sm[kk][bb] = Scur[(size_t)bb * NRES + k0 + kk];
        }
        // W tile: BK x BN = 1024 floats, 4 per thread, coalesced on k
#pragma unroll
        for (int r = 0; r < 4; r++) {
            int i  = tid + 256 * r;
            int nn = i >> 5;
            int kk = i & 31;
            W_sm[kk][nn] = W_res[(size_t)(n0 + nn) * NRES + k0 + kk];
        }
        __syncthreads();

#pragma unroll
        for (int kk = 0; kk < BK; kk++) {
            float4 sv = *(const float4*)&S_sm[kk][tx * 4];
            float  w0 = W_sm[kk][ty * 2 + 0];
            float  w1 = W_sm[kk][ty * 2 + 1];
            acc[0][0] += sv.x * w0;  acc[0][1] += sv.x * w1;
            acc[1][0] += sv.y * w0;  acc[1][1] += sv.y * w1;
            acc[2][0] += sv.z * w0;  acc[2][1] += sv.z * w1;
            acc[3][0] += sv.w * w0;  acc[3][1] += sv.w * w1;
        }
        __syncthreads();
    }

    // Fused LIF epilogue
#pragma unroll
    for (int i = 0; i < 4; i++) {
        int   b   = tx * 4 + i;
        float xin = x[b * TSTEPS + t];          // x is [B, 1, T]
#pragma unroll
        for (int j = 0; j < 2; j++) {
            int   n   = n0 + ty * 2 + j;
            float cur = acc[i][j] + xin * W_in[n];
            int   idx = b * NRES + n;
            float v   = BETA * g_vr[idx] + cur;
            float s   = (v >= THRESH) ? 1.0f : 0.0f;
            g_vr[idx] = v * (1.0f - s);
            Snxt[idx] = s;
        }
    }
}

// ---------------------------------------------------------------------------
// Readout step t: dot = S_new[b,:] @ W_out[c,:], classifier LIF, count spikes.
// One CTA per batch, deterministic tree reduction.
// ---------------------------------------------------------------------------
__global__ __launch_bounds__(256) void step_readout(
    const float* __restrict__ W_out,
    float* __restrict__ out,
    int t)
{
    __shared__ float red[256];
    __shared__ float dotv[NCLS];

    const int b   = blockIdx.x;
    const int tid = threadIdx.x;
    const float* __restrict__ S = g_S[(t + 1) & 1] + (size_t)b * NRES;

    for (int c = 0; c < NCLS; c++) {
        float p = 0.0f;
        for (int k = tid; k < NRES; k += 256)
            p += S[k] * W_out[(size_t)c * NRES + k];
        red[tid] = p;
        __syncthreads();
#pragma unroll
        for (int off = 128; off > 0; off >>= 1) {
            if (tid < off) red[tid] += red[tid + off];
            __syncthreads();
        }
        if (tid == 0) dotv[c] = red[0];
        __syncthreads();
    }

    if (tid < NCLS) {
        int   idx = b * NCLS + tid;
        float v   = BETA * g_vc[idx] + dotv[tid];
        float s   = (v >= THRESH) ? 1.0f : 0.0f;
        g_vc[idx] = v * (1.0f - s);
        out[idx] += s;
    }
}

// ---------------------------------------------------------------------------
extern "C" void kernel_launch(void* const* d_in, const int* in_sizes, int n_in,
                              void* d_out, int out_size)
{
    const float* x     = (const float*)d_in[0];  // [64,1,128]
    const float* W_in  = (const float*)d_in[1];  // [4096,1]
    const float* W_res = (const float*)d_in[2];  // [4096,4096]
    const float* W_out = (const float*)d_in[3];  // [10,4096]
    float*       out   = (float*)d_out;          // [64,10]

    init_kernel<<<(BATCH * NRES + 255) / 256, 256>>>(out);

    for (int t = 0; t < TSTEPS; t++) {
        step_reservoir<<<NRES / BN, 256>>>(x, W_in, W_res, t);
        step_readout<<<BATCH, 256>>>(W_out, out, t);
    }
}

// round 6
// speedup vs baseline: 1.5584x; 1.5584x over previous
#include <cuda_runtime.h>
#include <cstdint>

#define BATCH  64
#define NRES   4096
#define TSTEPS 128
#define NCLS   10

#define KSPLIT 4
#define MTILE  128
#define BKC    128                      // s8 k-elems per chunk (128B rows)
#define NKT    (NRES / KSPLIT / BKC)    // 8 k-chunks per split range
#define NLIMB  5
#define NCHUNK (NLIMB * NKT)            // 40
#define SCALE  137438953472.0           // 2^37

// smem: per buffer A 16KB + B 8KB; double buffered
#define SM_BUF   24576
#define SM_TOTAL 49152

// ---------------- device scratch (no runtime allocation) ----------------
__device__ int8_t   g_L[NLIMB][NRES * NRES];     // balanced radix-128 digits of W*2^37
__device__ int8_t   g_Sq[BATCH * NRES];          // spikes 0/1, [b][k]
__device__ long long g_part[KSPLIT * NRES * BATCH];  // exact int64 partial dots [ks][n][b]
__device__ float    g_vr[NRES * BATCH];          // [n][b]
__device__ float    g_vc[BATCH * NCLS];

// ---------------- helpers ----------------
__device__ __forceinline__ uint32_t smem_u32(const void* p) {
    uint32_t a;
    asm("{ .reg .u64 t; cvta.to.shared.u64 t, %1; cvt.u32.u64 %0, t; }" : "=r"(a) : "l"(p));
    return a;
}
#define SWZ(off) ((off) ^ (((off) >> 3) & 0x70))

__device__ __forceinline__ void cp16(uint32_t dst, const void* src) {
    asm volatile("cp.async.cg.shared.global [%0], [%1], 16;" :: "r"(dst), "l"(src) : "memory");
}
__device__ __forceinline__ void ldmx4(uint32_t* r, uint32_t a) {
    asm volatile("ldmatrix.sync.aligned.m8n8.x4.shared.b16 {%0,%1,%2,%3}, [%4];"
                 : "=r"(r[0]), "=r"(r[1]), "=r"(r[2]), "=r"(r[3]) : "r"(a));
}
__device__ __forceinline__ void ldmx2(uint32_t* r, uint32_t a) {
    asm volatile("ldmatrix.sync.aligned.m8n8.x2.shared.b16 {%0,%1}, [%2];"
                 : "=r"(r[0]), "=r"(r[1]) : "r"(a));
}
// int8 MMA, exact s32 accumulate (base ISA, sm_80+)
__device__ __forceinline__ void imma16832(int* d, const uint32_t* a, const uint32_t* b) {
    asm volatile(
        "mma.sync.aligned.m16n8k32.row.col.s32.s8.s8.s32 "
        "{%0,%1,%2,%3}, {%4,%5,%6,%7}, {%8,%9}, {%0,%1,%2,%3};"
        : "+r"(d[0]), "+r"(d[1]), "+r"(d[2]), "+r"(d[3])
        : "r"(a[0]), "r"(a[1]), "r"(a[2]), "r"(a[3]), "r"(b[0]), "r"(b[1]));
}

// ---------------------------------------------------------------------------
// Once per replay: v = round(w * 2^37); 5 balanced radix-128 digits,
// w*2^37 = sum_j d_j * 128^j, d_j in [-64,63]. |w| < 0.13 covered.
// ---------------------------------------------------------------------------
__global__ __launch_bounds__(256) void split_w(const float* __restrict__ W) {
    size_t i = (size_t)blockIdx.x * 256 + threadIdx.x;
    long long v = __double2ll_rn((double)W[i] * SCALE);
#pragma unroll
    for (int j = 0; j < NLIMB; j++) {
        long long d = ((v + 64) & 127) - 64;
        g_L[j][i] = (int8_t)d;
        v = (v - d) >> 7;
    }
}

__global__ __launch_bounds__(256) void init_state(float* __restrict__ out) {
    int i = blockIdx.x * 256 + threadIdx.x;
    if (i < BATCH * NRES) {
        g_Sq[i] = 0;
        g_vr[i] = 0.0f;
    }
    if (i < BATCH * NCLS) {
        g_vc[i] = 0.0f;
        out[i]  = 0.0f;
    }
}

// ---------------------------------------------------------------------------
// step_mma: exact integer dot: g_part[ks][n][b] = sum_k round(W[n,k]*2^37)*S[b,k]
// 5 digit-GEMMs (s8 x s8 -> s32, exact), MSB-first int64 fold t=(t<<7)+acc.
// grid = 128 CTAs (mtile*4 + ksplit), 256 threads (8 warps, 4x2 M x N),
// warp tile 32x32, cp.async double-buffered smem.
// ---------------------------------------------------------------------------
__global__ __launch_bounds__(256, 1) void step_mma() {
    extern __shared__ __align__(1024) char smem[];
    const int tid  = threadIdx.x;
    const int lane = tid & 31;
    const int warp = tid >> 5;
    const int wm   = warp >> 1;          // 0..3 (M)
    const int wn   = warp & 1;           // 0..1 (N)
    const int mt   = blockIdx.x >> 2;
    const int ks   = blockIdx.x & 3;
    const int m0   = mt * MTILE;
    const int kbase = ks * (NRES / KSPLIT);
    const uint32_t sbase = smem_u32(smem);

    int       acc[2][4][4];
    long long tt [2][4][4];
#pragma unroll
    for (int mi = 0; mi < 2; mi++)
#pragma unroll
        for (int ni = 0; ni < 4; ni++)
#pragma unroll
            for (int j = 0; j < 4; j++) { acc[mi][ni][j] = 0; tt[mi][ni][j] = 0; }

    auto issue = [&](int c) {
        const int buf = c & 1;
        const int li  = c >> 3;                     // 0..4, MSB-first
        const int kt  = c & 7;
        const int8_t* Wp = g_L[(NLIMB - 1) - li];
        const int k0 = kbase + kt * BKC;
        const uint32_t abuf = sbase + buf * SM_BUF;
        const uint32_t bbuf = abuf + 16384;
        // A tile: 128 rows x 128B (s8), 1024 x 16B, 4 per thread
#pragma unroll
        for (int r = 0; r < 4; r++) {
            int i = tid + 256 * r, row = i >> 3, c8 = i & 7;
            cp16(abuf + SWZ(row * 128 + c8 * 16),
                 Wp + (size_t)(m0 + row) * NRES + k0 + c8 * 16);
        }
        // B tile: 64 rows x 128B (s8), 512 x 16B, 2 per thread
#pragma unroll
        for (int r = 0; r < 2; r++) {
            int i = tid + 256 * r, row = i >> 3, c8 = i & 7;
            cp16(bbuf + SWZ(row * 128 + c8 * 16),
                 g_Sq + (size_t)row * NRES + k0 + c8 * 16);
        }
        asm volatile("cp.async.commit_group;" ::: "memory");
    };

    issue(0);
    for (int c = 0; c < NCHUNK; c++) {
        if (c + 1 < NCHUNK) {
            issue(c + 1);
            asm volatile("cp.async.wait_group 1;" ::: "memory");
        } else {
            asm volatile("cp.async.wait_group 0;" ::: "memory");
        }
        __syncthreads();

        const uint32_t abuf = sbase + (c & 1) * SM_BUF;
        const uint32_t bbuf = abuf + 16384;
        const int arow  = wm * 32 + (lane & 15);
        const int acolx = (lane >> 4) << 4;          // +16B = s8 k 16..31 half
        const int brow  = wn * 32 + (lane & 7);
        const int bcolx = ((lane >> 3) & 1) << 4;

#pragma unroll
        for (int kk = 0; kk < 4; kk++) {             // 4 x k32 per 128-k chunk
            uint32_t a[2][4], b[4][2];
#pragma unroll
            for (int mi = 0; mi < 2; mi++)
                ldmx4(a[mi], abuf + SWZ((arow + mi * 16) * 128 + kk * 32 + acolx));
#pragma unroll
            for (int ni = 0; ni < 4; ni++)
                ldmx2(b[ni], bbuf + SWZ((brow + ni * 8) * 128 + kk * 32 + bcolx));
#pragma unroll
            for (int mi = 0; mi < 2; mi++)
#pragma unroll
                for (int ni = 0; ni < 4; ni++)
                    imma16832(acc[mi][ni], a[mi], b[ni]);
        }
        __syncthreads();

        if ((c & 7) == 7) {   // limb finished: exact MSB-first fold
#pragma unroll
            for (int mi = 0; mi < 2; mi++)
#pragma unroll
                for (int ni = 0; ni < 4; ni++)
#pragma unroll
                    for (int j = 0; j < 4; j++) {
                        tt[mi][ni][j] = (tt[mi][ni][j] << 7) + (long long)acc[mi][ni][j];
                        acc[mi][ni][j] = 0;
                    }
        }
    }

    // Epilogue: c0,c1 -> (row g, col 2t,2t+1); c2,c3 -> row g+8.
    const int g = lane >> 2, t4 = lane & 3;
#pragma unroll
    for (int mi = 0; mi < 2; mi++)
#pragma unroll
        for (int ni = 0; ni < 4; ni++) {
            int row = m0 + wm * 32 + mi * 16 + g;
            int col = wn * 32 + ni * 8 + t4 * 2;
            longlong2 v0 = make_longlong2(tt[mi][ni][0], tt[mi][ni][1]);
            longlong2 v1 = make_longlong2(tt[mi][ni][2], tt[mi][ni][3]);
            *(longlong2*)(g_part + ((size_t)(ks * NRES + row)) * BATCH + col)     = v0;
            *(longlong2*)(g_part + ((size_t)(ks * NRES + row + 8)) * BATCH + col) = v1;
        }
}

// ---------------------------------------------------------------------------
// step_lif: exact int64 combine of 4 K-splits, single f64->f32 rounding,
// reference-op-structured fp32 LIF (no FMA contraction), write s8 spikes.
// ---------------------------------------------------------------------------
__global__ __launch_bounds__(256) void step_lif(const float* __restrict__ x,
                                                const float* __restrict__ W_in, int t) {
    int i = blockIdx.x * 256 + threadIdx.x;   // i = n*64 + b
    int n = i >> 6, b = i & 63;
    long long T = (g_part[i] + g_part[NRES * BATCH + i])
                + (g_part[2 * NRES * BATCH + i] + g_part[3 * NRES * BATCH + i]);
    float dotf = (float)((double)T * (1.0 / SCALE));
    float xw   = __fmul_rn(x[b * TSTEPS + t], W_in[n]);
    float cur  = __fadd_rn(xw, dotf);
    float v    = __fadd_rn(__fmul_rn(0.9f, g_vr[i]), cur);
    float s    = (v >= 1.0f) ? 1.0f : 0.0f;
    g_vr[i] = v * (1.0f - s);
    g_Sq[(size_t)b * NRES + n] = (int8_t)s;
}

// ---------------------------------------------------------------------------
// step_readout: fp64-accumulated dots (near-exact), classifier LIF, count.
// ---------------------------------------------------------------------------
__global__ __launch_bounds__(256) void step_readout(const float* __restrict__ W_out,
                                                    float* __restrict__ out, int t) {
    __shared__ double red[8][NCLS];
    const int b = blockIdx.x, tid = threadIdx.x;
    const int k0 = tid * 16;

    float s[16];
    const int8_t* S = g_Sq + (size_t)b * NRES + k0;
#pragma unroll
    for (int j = 0; j < 16; j++) s[j] = (float)S[j];

    double acc[NCLS];
#pragma unroll
    for (int c = 0; c < NCLS; c++) {
        const float* W = W_out + (size_t)c * NRES + k0;
        double a = 0.0;
#pragma unroll
        for (int j = 0; j < 16; j++) a += (double)s[j] * (double)W[j];
        acc[c] = a;
    }
#pragma unroll
    for (int c = 0; c < NCLS; c++)
#pragma unroll
        for (int o = 16; o > 0; o >>= 1)
            acc[c] += __shfl_down_sync(0xffffffff, acc[c], o);
    if ((tid & 31) == 0)
#pragma unroll
        for (int c = 0; c < NCLS; c++) red[tid >> 5][c] = acc[c];
    __syncthreads();

    if (tid < NCLS) {
        double dot = 0.0;
#pragma unroll
        for (int w = 0; w < 8; w++) dot += red[w][tid];
        int   idx = b * NCLS + tid;
        float v   = __fadd_rn(__fmul_rn(0.9f, g_vc[idx]), (float)dot);
        float sc  = (v >= 1.0f) ? 1.0f : 0.0f;
        g_vc[idx] = v * (1.0f - sc);
        out[idx] += sc;
    }
}

// ---------------------------------------------------------------------------
extern "C" void kernel_launch(void* const* d_in, const int* in_sizes, int n_in,
                              void* d_out, int out_size)
{
    const float* x     = (const float*)d_in[0];  // [64,1,128]
    const float* W_in  = (const float*)d_in[1];  // [4096,1]
    const float* W_res = (const float*)d_in[2];  // [4096,4096]
    const float* W_out = (const float*)d_in[3];  // [10,4096]
    float*       out   = (float*)d_out;          // [64,10]

    cudaFuncSetAttribute(step_mma, cudaFuncAttributeMaxDynamicSharedMemorySize, SM_TOTAL);

    split_w<<<(NRES * NRES) / 256, 256>>>(W_res);
    init_state<<<BATCH * NRES / 256, 256>>>(out);

    for (int t = 0; t < TSTEPS; t++) {
        step_mma<<<128, 256, SM_TOTAL>>>();
        step_lif<<<NRES * BATCH / 256, 256>>>(x, W_in, t);
        step_readout<<<BATCH, 256>>>(W_out, out, t);
    }
}

// round 7
// speedup vs baseline: 1.8057x; 1.1587x over previous
#include <cuda_runtime.h>
#include <cstdint>

#define BATCH  64
#define NRES   4096
#define TSTEPS 128
#define NCLS   10

#define KSPLIT 4
#define MTILE  128
#define BKC    128                      // s8 k-elems per chunk (128B rows)
#define NKT    (NRES / KSPLIT / BKC)    // 8 k-chunks per split range
#define NLIMB  4
#define NCHUNK (NLIMB * NKT)            // 32
#define SCALE  8589934592.0             // 2^33

#define NSTAGE   4
#define SM_BUF   24576                  // A 16KB + B 8KB per stage
#define SM_TOTAL (NSTAGE * SM_BUF)      // 98304

// ---------------- device scratch (no runtime allocation) ----------------
__device__ int8_t    g_L[NLIMB][NRES * NRES];      // balanced radix-256 digits of W*2^33
__device__ int8_t    g_Sq[BATCH * NRES];           // spikes 0/1, [b][k]
__device__ long long g_part[KSPLIT * NRES * BATCH];// exact int64 partial dots [ks][n][b]
__device__ float     g_vr[NRES * BATCH];           // [n][b]
__device__ float     g_vc[BATCH * NCLS];

// ---------------- helpers ----------------
__device__ __forceinline__ uint32_t smem_u32(const void* p) {
    uint32_t a;
    asm("{ .reg .u64 t; cvta.to.shared.u64 t, %1; cvt.u32.u64 %0, t; }" : "=r"(a) : "l"(p));
    return a;
}
#define SWZ(off) ((off) ^ (((off) >> 3) & 0x70))

__device__ __forceinline__ void cp16(uint32_t dst, const void* src) {
    asm volatile("cp.async.cg.shared.global [%0], [%1], 16;" :: "r"(dst), "l"(src) : "memory");
}
__device__ __forceinline__ void ldmx4(uint32_t* r, uint32_t a) {
    asm volatile("ldmatrix.sync.aligned.m8n8.x4.shared.b16 {%0,%1,%2,%3}, [%4];"
                 : "=r"(r[0]), "=r"(r[1]), "=r"(r[2]), "=r"(r[3]) : "r"(a));
}
__device__ __forceinline__ void ldmx2(uint32_t* r, uint32_t a) {
    asm volatile("ldmatrix.sync.aligned.m8n8.x2.shared.b16 {%0,%1}, [%2];"
                 : "=r"(r[0]), "=r"(r[1]) : "r"(a));
}
__device__ __forceinline__ void imma16832(int* d, const uint32_t* a, const uint32_t* b) {
    asm volatile(
        "mma.sync.aligned.m16n8k32.row.col.s32.s8.s8.s32 "
        "{%0,%1,%2,%3}, {%4,%5,%6,%7}, {%8,%9}, {%0,%1,%2,%3};"
        : "+r"(d[0]), "+r"(d[1]), "+r"(d[2]), "+r"(d[3])
        : "r"(a[0]), "r"(a[1]), "r"(a[2]), "r"(a[3]), "r"(b[0]), "r"(b[1]));
}

// ---------------------------------------------------------------------------
// Once per replay: v = round(w * 2^33); 4 balanced radix-256 digits,
// v = sum_j d_j * 256^j, d_j in [-128,127]. Capacity ±2^31 >> |v|max ~2^30.
// ---------------------------------------------------------------------------
__global__ __launch_bounds__(256) void split_w(const float* __restrict__ W) {
    size_t i = (size_t)blockIdx.x * 256 + threadIdx.x;
    long long v = __double2ll_rn((double)W[i] * SCALE);
#pragma unroll
    for (int j = 0; j < NLIMB; j++) {
        long long d = ((v + 128) & 255) - 128;
        g_L[j][i] = (int8_t)d;
        v = (v - d) >> 8;
    }
}

__global__ __launch_bounds__(256) void init_state(float* __restrict__ out) {
    int i = blockIdx.x * 256 + threadIdx.x;
    if (i < BATCH * NRES) {
        g_Sq[i] = 0;
        g_vr[i] = 0.0f;
    }
    if (i < BATCH * NCLS) {
        g_vc[i] = 0.0f;
        out[i]  = 0.0f;
    }
}

// ---------------------------------------------------------------------------
// step_mma: exact g_part[ks][n][b] = sum_k round(W[n,k]*2^33) * S[b,k].
// 4 digit-GEMMs (s8 -> s32 exact), MSB-first fold tt = (tt<<8) + acc.
// grid = 128 CTAs (mtile*4 + ks), 512 threads = 16 warps (4M x 4N),
// warp tile 32x16. 4-stage cp.async pipeline, one __syncthreads per chunk.
// ---------------------------------------------------------------------------
__global__ __launch_bounds__(512, 1) void step_mma() {
    extern __shared__ __align__(1024) char smem[];
    const int tid  = threadIdx.x;
    const int lane = tid & 31;
    const int warp = tid >> 5;
    const int wm   = warp & 3;           // 0..3 (M, 32 rows each)
    const int wn   = warp >> 2;          // 0..3 (N, 16 cols each)
    const int mt   = blockIdx.x >> 2;
    const int ks   = blockIdx.x & 3;
    const int m0   = mt * MTILE;
    const int kbase = ks * (NRES / KSPLIT);
    const uint32_t sbase = smem_u32(smem);

    int       acc[2][2][4];
    long long tt [2][2][4];
#pragma unroll
    for (int mi = 0; mi < 2; mi++)
#pragma unroll
        for (int ni = 0; ni < 2; ni++)
#pragma unroll
            for (int j = 0; j < 4; j++) { acc[mi][ni][j] = 0; tt[mi][ni][j] = 0; }

    auto issue = [&](int c) {
        const int li = c >> 3;                     // limb index, MSB-first
        const int kt = c & 7;
        const int8_t* Wp = g_L[(NLIMB - 1) - li];
        const int k0 = kbase + kt * BKC;
        const uint32_t abuf = sbase + (c & (NSTAGE - 1)) * SM_BUF;
        const uint32_t bbuf = abuf + 16384;
        // A tile: 128 rows x 128B s8 = 1024 x 16B, 2 per thread
#pragma unroll
        for (int r = 0; r < 2; r++) {
            int i = tid + 512 * r, row = i >> 3, c8 = i & 7;
            cp16(abuf + SWZ(row * 128 + c8 * 16),
                 Wp + (size_t)(m0 + row) * NRES + k0 + c8 * 16);
        }
        // B tile: 64 rows x 128B s8 = 512 x 16B, 1 per thread
        {
            int row = tid >> 3, c8 = tid & 7;
            cp16(bbuf + SWZ(row * 128 + c8 * 16),
                 g_Sq + (size_t)row * NRES + k0 + c8 * 16);
        }
        asm volatile("cp.async.commit_group;" ::: "memory");
    };

    issue(0); issue(1); issue(2);

    const int arow  = wm * 32 + (lane & 15);
    const int acolx = (lane >> 4) << 4;
    const int brow  = wn * 16 + (lane & 7);
    const int bcolx = ((lane >> 3) & 1) << 4;

    for (int c = 0; c < NCHUNK; c++) {
        asm volatile("cp.async.wait_group 2;" ::: "memory");
        __syncthreads();                 // chunk c visible to all; reads of buf (c+3)%4 done
        if (c + 3 < NCHUNK) issue(c + 3);

        const uint32_t abuf = sbase + (c & (NSTAGE - 1)) * SM_BUF;
        const uint32_t bbuf = abuf + 16384;

#pragma unroll
        for (int kk = 0; kk < 4; kk++) {             // 4 x k32 per 128-k chunk
            uint32_t a[2][4], b[2][2];
#pragma unroll
            for (int mi = 0; mi < 2; mi++)
                ldmx4(a[mi], abuf + SWZ((arow + mi * 16) * 128 + kk * 32 + acolx));
#pragma unroll
            for (int ni = 0; ni < 2; ni++)
                ldmx2(b[ni], bbuf + SWZ((brow + ni * 8) * 128 + kk * 32 + bcolx));
#pragma unroll
            for (int mi = 0; mi < 2; mi++)
#pragma unroll
                for (int ni = 0; ni < 2; ni++)
                    imma16832(acc[mi][ni], a[mi], b[ni]);
        }

        if ((c & 7) == 7) {              // limb done: exact MSB-first radix-256 fold
#pragma unroll
            for (int mi = 0; mi < 2; mi++)
#pragma unroll
                for (int ni = 0; ni < 2; ni++)
#pragma unroll
                    for (int j = 0; j < 4; j++) {
                        tt[mi][ni][j] = (tt[mi][ni][j] << 8) + (long long)acc[mi][ni][j];
                        acc[mi][ni][j] = 0;
                    }
        }
    }

    // Epilogue: c0,c1 -> (row g, col 2t,2t+1); c2,c3 -> row g+8.
    const int g = lane >> 2, t4 = lane & 3;
#pragma unroll
    for (int mi = 0; mi < 2; mi++)
#pragma unroll
        for (int ni = 0; ni < 2; ni++) {
            int row = m0 + wm * 32 + mi * 16 + g;
            int col = wn * 16 + ni * 8 + t4 * 2;
            longlong2 v0 = make_longlong2(tt[mi][ni][0], tt[mi][ni][1]);
            longlong2 v1 = make_longlong2(tt[mi][ni][2], tt[mi][ni][3]);
            *(longlong2*)(g_part + ((size_t)(ks * NRES + row)) * BATCH + col)     = v0;
            *(longlong2*)(g_part + ((size_t)(ks * NRES + row + 8)) * BATCH + col) = v1;
        }
}

// ---------------------------------------------------------------------------
// step_lif: exact int64 combine of 4 K-splits, single f64->f32 rounding,
// reference-op-structured fp32 LIF, write s8 spikes [b][k].
// ---------------------------------------------------------------------------
__global__ __launch_bounds__(256) void step_lif(const float* __restrict__ x,
                                                const float* __restrict__ W_in, int t) {
    int i = blockIdx.x * 256 + threadIdx.x;   // i = n*64 + b
    int n = i >> 6, b = i & 63;
    long long T = (g_part[i] + g_part[NRES * BATCH + i])
                + (g_part[2 * NRES * BATCH + i] + g_part[3 * NRES * BATCH + i]);
    float dotf = (float)((double)T * (1.0 / SCALE));
    float xw   = __fmul_rn(x[b * TSTEPS + t], W_in[n]);
    float cur  = __fadd_rn(xw, dotf);
    float v    = __fadd_rn(__fmul_rn(0.9f, g_vr[i]), cur);
    float s    = (v >= 1.0f) ? 1.0f : 0.0f;
    g_vr[i] = v * (1.0f - s);
    g_Sq[(size_t)b * NRES + n] = (int8_t)s;
}

// ---------------------------------------------------------------------------
// step_readout: fp64-accumulated dots, classifier LIF, spike count.
// ---------------------------------------------------------------------------
__global__ __launch_bounds__(256) void step_readout(const float* __restrict__ W_out,
                                                    float* __restrict__ out, int t) {
    __shared__ double red[8][NCLS];
    const int b = blockIdx.x, tid = threadIdx.x;
    const int k0 = tid * 16;

    float s[16];
    const int8_t* S = g_Sq + (size_t)b * NRES + k0;
#pragma unroll
    for (int j = 0; j < 16; j++) s[j] = (float)S[j];

    double acc[NCLS];
#pragma unroll
    for (int c = 0; c < NCLS; c++) {
        const float* W = W_out + (size_t)c * NRES + k0;
        double a = 0.0;
#pragma unroll
        for (int j = 0; j < 16; j++) a += (double)s[j] * (double)W[j];
        acc[c] = a;
    }
#pragma unroll
    for (int c = 0; c < NCLS; c++)
#pragma unroll
        for (int o = 16; o > 0; o >>= 1)
            acc[c] += __shfl_down_sync(0xffffffff, acc[c], o);
    if ((tid & 31) == 0)
#pragma unroll
        for (int c = 0; c < NCLS; c++) red[tid >> 5][c] = acc[c];
    __syncthreads();

    if (tid < NCLS) {
        double dot = 0.0;
#pragma unroll
        for (int w = 0; w < 8; w++) dot += red[w][tid];
        int   idx = b * NCLS + tid;
        float v   = __fadd_rn(__fmul_rn(0.9f, g_vc[idx]), (float)dot);
        float sc  = (v >= 1.0f) ? 1.0f : 0.0f;
        g_vc[idx] = v * (1.0f - sc);
        out[idx] += sc;
    }
}

// ---------------------------------------------------------------------------
extern "C" void kernel_launch(void* const* d_in, const int* in_sizes, int n_in,
                              void* d_out, int out_size)
{
    const float* x     = (const float*)d_in[0];  // [64,1,128]
    const float* W_in  = (const float*)d_in[1];  // [4096,1]
    const float* W_res = (const float*)d_in[2];  // [4096,4096]
    const float* W_out = (const float*)d_in[3];  // [10,4096]
    float*       out   = (float*)d_out;          // [64,10]

    cudaFuncSetAttribute(step_mma, cudaFuncAttributeMaxDynamicSharedMemorySize, SM_TOTAL);

    split_w<<<(NRES * NRES) / 256, 256>>>(W_res);
    init_state<<<BATCH * NRES / 256, 256>>>(out);

    for (int t = 0; t < TSTEPS; t++) {
        step_mma<<<128, 512, SM_TOTAL>>>();
        step_lif<<<NRES * BATCH / 256, 256>>>(x, W_in, t);
        step_readout<<<BATCH, 256>>>(W_out, out, t);
    }
}